// round 1
// baseline (speedup 1.0000x reference)
#include <cuda_runtime.h>
#include <cuda_bf16.h>
#include <math.h>

// ----------------------------------------------------------------------------
// CAM cross-attention: B=16, S=D=1024
//   a1 = f1 @ W                 (NN gemm)
//   cc = a1 @ f2^T              (NT gemm)
//   m_c[t] = max_s cc[s,t] ; m_r[s] = max_t cc[s,t]
//   E_c[s,t] = exp(cc - m_c[t]) ; c[t] = colsum  -> out1[t,s] = (f1 @ E_c)^T[t,s] / c[t]   (TT gemm + row scale)
//   E_r[s,t] = exp(cc - m_r[s]) ; r[s] = rowsum  -> out2[s,t] = (E_r @ f2^T)[s,t] / r[s]   (NT gemm + row scale)
// Scratch: g_cc (kept), g_a1 (reused as E after cc is built).
// ----------------------------------------------------------------------------

#define NB 16
#define NN 1024
#define BM 128
#define BN 128
#define BK 16
#define PAD 4

__device__ float g_a1[(size_t)NB * NN * NN];   // 64 MB, reused as E
__device__ float g_cc[(size_t)NB * NN * NN];   // 64 MB
__device__ float g_mc[NB * NN];
__device__ float g_invc[NB * NN];
__device__ float g_invr[NB * NN];

// Generic 1024x1024x1024 tiled SGEMM.
// TA: A stored [K,M] (else [M,N-free: M,K]); TB: B stored [N,K] (else [K,N]).
// SCALE: multiply output row m by scale[b*1024+m].
template<bool TA, bool TB, bool SCALE>
__global__ __launch_bounds__(256, 2)
void sgemm_kernel(const float* __restrict__ Ag, const float* __restrict__ Bg,
                  float* __restrict__ Cg, const float* __restrict__ scaleg,
                  size_t sA, size_t sB, size_t sC)
{
    __shared__ float As[BK][BM + PAD];
    __shared__ float Bs[BK][BN + PAD];

    const int b = blockIdx.z;
    const float* A = Ag + (size_t)b * sA;
    const float* B = Bg + (size_t)b * sB;
    float* C = Cg + (size_t)b * sC;

    const int m0 = blockIdx.y * BM;
    const int n0 = blockIdx.x * BN;
    const int tid = threadIdx.x;
    const int tx = tid & 15;   // n direction (8 cols each)
    const int ty = tid >> 4;   // m direction (8 rows each)

    float acc[8][8];
    #pragma unroll
    for (int i = 0; i < 8; i++)
        #pragma unroll
        for (int j = 0; j < 8; j++) acc[i][j] = 0.0f;

    const int LD = NN;

    for (int k0 = 0; k0 < NN; k0 += BK) {
        // ---- load A tile into As[k][m] ----
        if (!TA) {
            // A[M,K]: 128 rows x 16 cols, transpose into smem
            #pragma unroll
            for (int i = 0; i < 2; i++) {
                int f = tid + i * 256;
                int row = f >> 2;            // 0..127 (m)
                int cv  = (f & 3) * 4;       // 0,4,8,12 (k)
                float4 v = *(const float4*)(A + (size_t)(m0 + row) * LD + k0 + cv);
                As[cv + 0][row] = v.x;
                As[cv + 1][row] = v.y;
                As[cv + 2][row] = v.z;
                As[cv + 3][row] = v.w;
            }
        } else {
            // A[K,M]: 16 rows x 128 cols, direct
            #pragma unroll
            for (int i = 0; i < 2; i++) {
                int f = tid + i * 256;
                int kr = f >> 5;             // 0..15 (k)
                int cv = (f & 31) * 4;       // 0..124 (m)
                float4 v = *(const float4*)(A + (size_t)(k0 + kr) * LD + m0 + cv);
                *(float4*)&As[kr][cv] = v;
            }
        }
        // ---- load B tile into Bs[k][n] ----
        if (!TB) {
            #pragma unroll
            for (int i = 0; i < 2; i++) {
                int f = tid + i * 256;
                int kr = f >> 5;
                int cv = (f & 31) * 4;
                float4 v = *(const float4*)(B + (size_t)(k0 + kr) * LD + n0 + cv);
                *(float4*)&Bs[kr][cv] = v;
            }
        } else {
            // B[N,K]: 128 rows x 16 cols, transpose into smem
            #pragma unroll
            for (int i = 0; i < 2; i++) {
                int f = tid + i * 256;
                int row = f >> 2;            // 0..127 (n)
                int cv  = (f & 3) * 4;       // k
                float4 v = *(const float4*)(B + (size_t)(n0 + row) * LD + k0 + cv);
                Bs[cv + 0][row] = v.x;
                Bs[cv + 1][row] = v.y;
                Bs[cv + 2][row] = v.z;
                Bs[cv + 3][row] = v.w;
            }
        }
        __syncthreads();

        #pragma unroll
        for (int k = 0; k < BK; k++) {
            float ra[8], rb[8];
            *(float4*)&ra[0] = *(const float4*)&As[k][ty * 8];
            *(float4*)&ra[4] = *(const float4*)&As[k][ty * 8 + 4];
            *(float4*)&rb[0] = *(const float4*)&Bs[k][tx * 8];
            *(float4*)&rb[4] = *(const float4*)&Bs[k][tx * 8 + 4];
            #pragma unroll
            for (int i = 0; i < 8; i++)
                #pragma unroll
                for (int j = 0; j < 8; j++)
                    acc[i][j] += ra[i] * rb[j];
        }
        __syncthreads();
    }

    // ---- epilogue ----
    #pragma unroll
    for (int i = 0; i < 8; i++) {
        int m = m0 + ty * 8 + i;
        float s = SCALE ? scaleg[b * NN + m] : 1.0f;
        #pragma unroll
        for (int j = 0; j < 8; j += 4) {
            float4 v;
            v.x = acc[i][j + 0] * s;
            v.y = acc[i][j + 1] * s;
            v.z = acc[i][j + 2] * s;
            v.w = acc[i][j + 3] * s;
            *(float4*)(C + (size_t)m * LD + n0 + tx * 8 + j) = v;
        }
    }
}

// Column max over s: m_c[b,t] = max_s cc[b,s,t]. Coalesced column walk.
__global__ void colmax_kernel(const float* __restrict__ cc, float* __restrict__ mc)
{
    int b = blockIdx.y;
    int t = blockIdx.x * 256 + threadIdx.x;
    const float* p = cc + ((size_t)b << 20) + t;
    float m = -INFINITY;
    #pragma unroll 8
    for (int s = 0; s < NN; s++)
        m = fmaxf(m, p[(size_t)s * NN]);
    mc[b * NN + t] = m;
}

// E[s,t] = exp(cc[s,t] - m_c[t]); inv_c[t] = 1 / colsum.
__global__ void expcol_kernel(const float* __restrict__ cc, const float* __restrict__ mc,
                              float* __restrict__ E, float* __restrict__ invc)
{
    int b = blockIdx.y;
    int t = blockIdx.x * 256 + threadIdx.x;
    size_t base = ((size_t)b << 20) + t;
    float m = mc[b * NN + t];
    float sum = 0.0f;
    #pragma unroll 4
    for (int s = 0; s < NN; s++) {
        float e = expf(cc[base + (size_t)s * NN] - m);
        sum += e;
        E[base + (size_t)s * NN] = e;
    }
    invc[b * NN + t] = 1.0f / sum;
}

// Per-row: m_r = max_t cc[s,t]; E[s,t] = exp(cc - m_r); inv_r[s] = 1/rowsum.
// One block (256 threads) per row; 4 elements per thread held in registers.
__global__ void exprow_kernel(const float* __restrict__ cc, float* __restrict__ E,
                              float* __restrict__ invr)
{
    __shared__ float red[256];
    int b = blockIdx.y, s = blockIdx.x;
    size_t base = ((size_t)b << 20) + ((size_t)s << 10);
    int t0 = threadIdx.x * 4;
    float4 q = *(const float4*)(cc + base + t0);
    float m = fmaxf(fmaxf(q.x, q.y), fmaxf(q.z, q.w));

    red[threadIdx.x] = m;
    __syncthreads();
    #pragma unroll
    for (int o = 128; o > 0; o >>= 1) {
        if (threadIdx.x < o) red[threadIdx.x] = fmaxf(red[threadIdx.x], red[threadIdx.x + o]);
        __syncthreads();
    }
    m = red[0];
    __syncthreads();

    float4 e;
    e.x = expf(q.x - m); e.y = expf(q.y - m);
    e.z = expf(q.z - m); e.w = expf(q.w - m);
    *(float4*)(E + base + t0) = e;

    red[threadIdx.x] = e.x + e.y + e.z + e.w;
    __syncthreads();
    #pragma unroll
    for (int o = 128; o > 0; o >>= 1) {
        if (threadIdx.x < o) red[threadIdx.x] += red[threadIdx.x + o];
        __syncthreads();
    }
    if (threadIdx.x == 0) invr[b * NN + s] = 1.0f / red[0];
}

extern "C" void kernel_launch(void* const* d_in, const int* in_sizes, int n_in,
                              void* d_out, int out_size)
{
    const float* f1 = (const float*)d_in[0];   // [16,1024,1024]
    const float* f2 = (const float*)d_in[1];   // [16,1024,1024]
    const float* W  = (const float*)d_in[2];   // [1024,1024]
    float* out1 = (float*)d_out;                              // [16,1024,1024]
    float* out2 = out1 + ((size_t)NB << 20);                  // [16,1024,1024]

    float *a1, *cc, *mc, *invc, *invr;
    cudaGetSymbolAddress((void**)&a1,   g_a1);
    cudaGetSymbolAddress((void**)&cc,   g_cc);
    cudaGetSymbolAddress((void**)&mc,   g_mc);
    cudaGetSymbolAddress((void**)&invc, g_invc);
    cudaGetSymbolAddress((void**)&invr, g_invr);

    const size_t MB = (size_t)1 << 20;
    dim3 gg(NN / BN, NN / BM, NB), gb(256);

    // 1. a1 = f1 @ W                        (NN, W shared across batch)
    sgemm_kernel<false, false, false><<<gg, gb>>>(f1, W, a1, nullptr, MB, 0, MB);
    // 2. cc = a1 @ f2^T                     (NT)
    sgemm_kernel<false, true, false><<<gg, gb>>>(a1, f2, cc, nullptr, MB, MB, MB);
    // 3. column maxes
    colmax_kernel<<<dim3(NN / 256, NB), 256>>>(cc, mc);
    // 4. E_c = exp(cc - m_c), inverse column sums   (E overwrites a1)
    expcol_kernel<<<dim3(NN / 256, NB), 256>>>(cc, mc, a1, invc);
    // 5. out1[t,s] = invc[t] * sum_d E_c[d,t] * f1[s,d]   (TT + row scale)
    sgemm_kernel<true, true, true><<<gg, gb>>>(a1, f1, out1, invc, MB, MB, MB);
    // 6. E_r = exp(cc - m_r), inverse row sums
    exprow_kernel<<<dim3(NN, NB), 256>>>(cc, a1, invr);
    // 7. out2[s,t] = invr[s] * sum_d E_r[s,d] * f2[t,d]   (NT + row scale)
    sgemm_kernel<false, true, true><<<gg, gb>>>(a1, f2, out2, invr, MB, MB, MB);
}

// round 3
// speedup vs baseline: 2.2604x; 2.2604x over previous
#include <cuda_runtime.h>
#include <cuda_bf16.h>
#include <math.h>
#include <stdint.h>

#define NB 16
#define NN 1024

// ---------------- helpers ----------------
__device__ __forceinline__ uint32_t smem_to_u32(const void* p) {
    uint32_t a;
    asm("{ .reg .u64 t; cvta.to.shared.u64 t, %1; cvt.u32.u64 %0, t; }" : "=r"(a) : "l"(p));
    return a;
}
__device__ __forceinline__ void cp16(uint32_t dst, const void* src) {
    asm volatile("cp.async.cg.shared.global [%0], [%1], 16;" :: "r"(dst), "l"(src));
}
__device__ __forceinline__ void cp_commit() { asm volatile("cp.async.commit_group;" ::: "memory"); }
__device__ __forceinline__ void cp_wait1()  { asm volatile("cp.async.wait_group 1;" ::: "memory"); }

__device__ __forceinline__ void ldsm4(uint32_t* r, uint32_t addr) {
    asm volatile("ldmatrix.sync.aligned.m8n8.x4.shared.b16 {%0,%1,%2,%3}, [%4];"
                 : "=r"(r[0]), "=r"(r[1]), "=r"(r[2]), "=r"(r[3]) : "r"(addr));
}
__device__ __forceinline__ void mma_bf16(float* c, const uint32_t* a, const uint32_t* b) {
    asm volatile(
        "mma.sync.aligned.m16n8k16.row.col.f32.bf16.bf16.f32 "
        "{%0,%1,%2,%3}, {%4,%5,%6,%7}, {%8,%9}, {%0,%1,%2,%3};"
        : "+f"(c[0]), "+f"(c[1]), "+f"(c[2]), "+f"(c[3])
        : "r"(a[0]), "r"(a[1]), "r"(a[2]), "r"(a[3]), "r"(b[0]), "r"(b[1]));
}

// ---------------- scratch (device globals) ----------------
#define TOT ((size_t)NB * NN * NN)
__device__ __nv_bfloat16 g_f1h[TOT], g_f1l[TOT];
__device__ __nv_bfloat16 g_f2h[TOT], g_f2l[TOT];
__device__ __nv_bfloat16 g_wth[NN * NN], g_wtl[NN * NN];
__device__ __nv_bfloat16 g_a1h[TOT], g_a1l[TOT];
__device__ __nv_bfloat16 g_eth[TOT], g_etl[TOT];
__device__ __nv_bfloat16 g_erh[TOT], g_erl[TOT];
__device__ float g_cc[TOT];
__device__ float g_part[NB * 8 * NN];
__device__ float g_mc[NB * NN], g_invc[NB * NN], g_invr[NB * NN];

// ---------------- split-2 bf16 GEMM via mma.sync ----------------
// C[M,N] = A[M,K] · B[N,K]^T, hi/lo split operands (3 products).
// Tile 128x128, BK=32, 8 warps (2 m x 4 n), warp tile 64x32, 3-stage cp.async.
#define BK 32
#define LDSROW 40                       // bf16 per smem row (32 + 8 pad)
#define ARRB (128 * LDSROW * 2)         // 10240 B per operand array
#define SLOTB (4 * ARRB)                // 40960 B per stage
#define NSTAGE 3
#define SMEM_DYN (NSTAGE * SLOTB)       // 122880 B
#define KT 32                           // k tiles

template<bool SPLIT_OUT, bool SCALE>
__global__ __launch_bounds__(256, 1)
void gemm_kernel(const __nv_bfloat16* __restrict__ Ah, const __nv_bfloat16* __restrict__ Al,
                 const __nv_bfloat16* __restrict__ Bh, const __nv_bfloat16* __restrict__ Bl,
                 float* __restrict__ C, __nv_bfloat16* __restrict__ Ch, __nv_bfloat16* __restrict__ Cl,
                 const float* __restrict__ scaleg, size_t sA, size_t sB, size_t sC)
{
    extern __shared__ char dsm[];
    const uint32_t sb = smem_to_u32(dsm);

    const int tid = threadIdx.x;
    const int lane = tid & 31;
    const int w = tid >> 5;
    const int wm = w & 1;        // 0..1 -> 64 rows each
    const int wn = w >> 1;       // 0..3 -> 32 cols each
    const int b = blockIdx.z;
    const int m0 = blockIdx.y * 128;
    const int n0 = blockIdx.x * 128;

    Ah += (size_t)b * sA; Al += (size_t)b * sA;
    Bh += (size_t)b * sB; Bl += (size_t)b * sB;

    float acc[4][4][4];
    #pragma unroll
    for (int i = 0; i < 4; i++)
        #pragma unroll
        for (int j = 0; j < 4; j++)
            #pragma unroll
            for (int q = 0; q < 4; q++) acc[i][j][q] = 0.0f;

    // stage loader: 4 arrays x 128 rows x 2 chunks-of-16B-per-thread-pass
    auto load_stage = [&](int slot, int kt) {
        uint32_t base = sb + slot * SLOTB;
        int k0 = kt * BK;
        #pragma unroll
        for (int i = 0; i < 2; i++) {
            int f = tid + i * 256;
            int row = f >> 2, ch = f & 3;
            uint32_t so = row * (LDSROW * 2) + ch * 16;
            size_t gA = ((size_t)(m0 + row) << 10) + k0 + ch * 8;
            size_t gB = ((size_t)(n0 + row) << 10) + k0 + ch * 8;
            cp16(base + 0 * ARRB + so, Ah + gA);
            cp16(base + 1 * ARRB + so, Al + gA);
            cp16(base + 2 * ARRB + so, Bh + gB);
            cp16(base + 3 * ARRB + so, Bl + gB);
        }
    };

    load_stage(0, 0); cp_commit();
    load_stage(1, 1); cp_commit();

    // per-lane ldmatrix address pieces
    const int arow = wm * 64 + (lane & 15);          // + mt*16
    const int achk_l = lane >> 4;                    // + 2*ks
    const int brow = wn * 32 + ((lane & 16) >> 1) + (lane & 7);  // + p*16
    const int bchk_l = (lane >> 3) & 1;              // + 2*ks

    for (int kt = 0; kt < KT; kt++) {
        cp_wait1();
        __syncthreads();
        if (kt + 2 < KT) load_stage((kt + 2) % NSTAGE, kt + 2);
        cp_commit();

        uint32_t sa = sb + (kt % NSTAGE) * SLOTB;
        #pragma unroll
        for (int ks = 0; ks < 2; ks++) {
            uint32_t a_h[4][4], a_l[4][4], b_h[2][4], b_l[2][4];
            #pragma unroll
            for (int mt = 0; mt < 4; mt++) {
                uint32_t ad = sa + (arow + mt * 16) * (LDSROW * 2) + (ks * 2 + achk_l) * 16;
                ldsm4(a_h[mt], ad);
                ldsm4(a_l[mt], ad + ARRB);
            }
            #pragma unroll
            for (int p = 0; p < 2; p++) {
                uint32_t bd = sa + 2 * ARRB + (brow + p * 16) * (LDSROW * 2) + (ks * 2 + bchk_l) * 16;
                ldsm4(b_h[p], bd);
                ldsm4(b_l[p], bd + ARRB);
            }
            #pragma unroll
            for (int mt = 0; mt < 4; mt++)
                #pragma unroll
                for (int nt = 0; nt < 4; nt++) {
                    const uint32_t* bh = &b_h[nt >> 1][(nt & 1) * 2];
                    const uint32_t* bl = &b_l[nt >> 1][(nt & 1) * 2];
                    mma_bf16(acc[mt][nt], a_h[mt], bh);
                    mma_bf16(acc[mt][nt], a_h[mt], bl);
                    mma_bf16(acc[mt][nt], a_l[mt], bh);
                }
        }
    }

    // ---- epilogue: direct global stores ----
    #pragma unroll
    for (int mt = 0; mt < 4; mt++) {
        int mr = m0 + wm * 64 + mt * 16 + (lane >> 2);
        float s0 = 1.0f, s1 = 1.0f;
        if (SCALE) {
            s0 = scaleg[b * NN + mr];
            s1 = scaleg[b * NN + mr + 8];
        }
        #pragma unroll
        for (int nt = 0; nt < 4; nt++) {
            int nc = n0 + wn * 32 + nt * 8 + (lane & 3) * 2;
            size_t i0 = (size_t)b * sC + ((size_t)mr << 10) + nc;
            size_t i1 = i0 + (8 << 10);
            float v00 = acc[mt][nt][0] * s0, v01 = acc[mt][nt][1] * s0;
            float v10 = acc[mt][nt][2] * s1, v11 = acc[mt][nt][3] * s1;
            if (SPLIT_OUT) {
                __nv_bfloat16 h00 = __float2bfloat16(v00), h01 = __float2bfloat16(v01);
                __nv_bfloat16 h10 = __float2bfloat16(v10), h11 = __float2bfloat16(v11);
                *(__nv_bfloat162*)(Ch + i0) = __nv_bfloat162(h00, h01);
                *(__nv_bfloat162*)(Ch + i1) = __nv_bfloat162(h10, h11);
                *(__nv_bfloat162*)(Cl + i0) = __nv_bfloat162(
                    __float2bfloat16(v00 - __bfloat162float(h00)),
                    __float2bfloat16(v01 - __bfloat162float(h01)));
                *(__nv_bfloat162*)(Cl + i1) = __nv_bfloat162(
                    __float2bfloat16(v10 - __bfloat162float(h10)),
                    __float2bfloat16(v11 - __bfloat162float(h11)));
            } else {
                *(float2*)(C + i0) = make_float2(v00, v01);
                *(float2*)(C + i1) = make_float2(v10, v11);
            }
        }
    }
}

// ---------------- elementwise / reduction kernels ----------------
__global__ void split_kernel(const float* __restrict__ x, __nv_bfloat16* __restrict__ h,
                             __nv_bfloat16* __restrict__ l)
{
    size_t i = ((size_t)blockIdx.x * 256 + threadIdx.x) * 4;
    float4 v = *(const float4*)(x + i);
    union { __nv_bfloat16 hh[4]; uint2 u; } ph, pl;
    float f[4] = {v.x, v.y, v.z, v.w};
    #pragma unroll
    for (int j = 0; j < 4; j++) {
        __nv_bfloat16 bb = __float2bfloat16(f[j]);
        ph.hh[j] = bb;
        pl.hh[j] = __float2bfloat16(f[j] - __bfloat162float(bb));
    }
    *(uint2*)(h + i) = ph.u;
    *(uint2*)(l + i) = pl.u;
}

__global__ void wtrans_kernel(const float* __restrict__ W, __nv_bfloat16* __restrict__ h,
                              __nv_bfloat16* __restrict__ l)
{
    __shared__ float tile[32][33];
    int e0 = blockIdx.x << 5, d0 = blockIdx.y << 5;
    int tx = threadIdx.x, ty = threadIdx.y;
    #pragma unroll
    for (int j = 0; j < 4; j++) {
        int r = ty + (j << 3);
        tile[r][tx] = W[(size_t)(d0 + r) * NN + e0 + tx];
    }
    __syncthreads();
    #pragma unroll
    for (int j = 0; j < 4; j++) {
        int r = ty + (j << 3);
        float v = tile[tx][r];                      // W[d0+tx][e0+r]
        __nv_bfloat16 hh = __float2bfloat16(v);
        size_t o = (size_t)(e0 + r) * NN + d0 + tx; // WT[e][d]
        h[o] = hh;
        l[o] = __float2bfloat16(v - __bfloat162float(hh));
    }
}

__global__ void pmax_kernel(const float* __restrict__ cc, float* __restrict__ part)
{
    int b = blockIdx.z, sc = blockIdx.y;
    int t = blockIdx.x * 256 + threadIdx.x;
    const float* p = cc + ((size_t)b << 20) + ((size_t)sc << 17) + t;
    float m = -INFINITY;
    #pragma unroll 8
    for (int s = 0; s < 128; s++) m = fmaxf(m, p[(size_t)s << 10]);
    part[((b << 3) + sc) * NN + t] = m;
}
__global__ void maxred_kernel(const float* __restrict__ part, float* __restrict__ mc)
{
    int b = blockIdx.y;
    int t = blockIdx.x * 256 + threadIdx.x;
    float m = -INFINITY;
    #pragma unroll
    for (int c = 0; c < 8; c++) m = fmaxf(m, part[((b << 3) + c) * NN + t]);
    mc[b * NN + t] = m;
}
__global__ void psum_kernel(const float* __restrict__ cc, const float* __restrict__ mc,
                            float* __restrict__ part)
{
    int b = blockIdx.z, sc = blockIdx.y;
    int t = blockIdx.x * 256 + threadIdx.x;
    const float* p = cc + ((size_t)b << 20) + ((size_t)sc << 17) + t;
    float mm = mc[b * NN + t];
    float sum = 0.0f;
    #pragma unroll 4
    for (int s = 0; s < 128; s++) sum += expf(p[(size_t)s << 10] - mm);
    part[((b << 3) + sc) * NN + t] = sum;
}
__global__ void sumred_kernel(const float* __restrict__ part, float* __restrict__ invc)
{
    int b = blockIdx.y;
    int t = blockIdx.x * 256 + threadIdx.x;
    float s = 0.0f;
    #pragma unroll
    for (int c = 0; c < 8; c++) s += part[((b << 3) + c) * NN + t];
    invc[b * NN + t] = 1.0f / s;
}

// E_T[t][s] = exp(cc[s][t] - mc[t]) split into bf16 hi/lo (transposed write)
__global__ void expT_kernel(const float* __restrict__ cc, const float* __restrict__ mc,
                            __nv_bfloat16* __restrict__ Eh, __nv_bfloat16* __restrict__ El)
{
    __shared__ float tile[32][33];
    int b = blockIdx.z;
    int s0 = blockIdx.x << 5, t0 = blockIdx.y << 5;
    int tx = threadIdx.x, ty = threadIdx.y;
    size_t cb = (size_t)b << 20;
    #pragma unroll
    for (int j = 0; j < 4; j++) {
        int r = ty + (j << 3);
        tile[r][tx] = cc[cb + ((size_t)(s0 + r) << 10) + t0 + tx];
    }
    __syncthreads();
    #pragma unroll
    for (int j = 0; j < 4; j++) {
        int r = ty + (j << 3);
        float m = mc[b * NN + t0 + r];
        float e = expf(tile[tx][r] - m);            // cc[s0+tx][t0+r]
        __nv_bfloat16 hh = __float2bfloat16(e);
        size_t o = cb + ((size_t)(t0 + r) << 10) + s0 + tx;
        Eh[o] = hh;
        El[o] = __float2bfloat16(e - __bfloat162float(hh));
    }
}

// row softmax: E_r split + invr
__global__ void exprow_kernel(const float* __restrict__ cc, __nv_bfloat16* __restrict__ Eh,
                              __nv_bfloat16* __restrict__ El, float* __restrict__ invr)
{
    __shared__ float red[256];
    int b = blockIdx.y, s = blockIdx.x;
    size_t base = ((size_t)b << 20) + ((size_t)s << 10);
    int t0 = threadIdx.x * 4;
    float4 q = *(const float4*)(cc + base + t0);
    float m = fmaxf(fmaxf(q.x, q.y), fmaxf(q.z, q.w));
    red[threadIdx.x] = m;
    __syncthreads();
    #pragma unroll
    for (int o = 128; o > 0; o >>= 1) {
        if (threadIdx.x < o) red[threadIdx.x] = fmaxf(red[threadIdx.x], red[threadIdx.x + o]);
        __syncthreads();
    }
    m = red[0];
    __syncthreads();
    float e[4] = {expf(q.x - m), expf(q.y - m), expf(q.z - m), expf(q.w - m)};
    union { __nv_bfloat16 h[4]; uint2 u; } ph, pl;
    #pragma unroll
    for (int j = 0; j < 4; j++) {
        __nv_bfloat16 hh = __float2bfloat16(e[j]);
        ph.h[j] = hh;
        pl.h[j] = __float2bfloat16(e[j] - __bfloat162float(hh));
    }
    *(uint2*)(Eh + base + t0) = ph.u;
    *(uint2*)(El + base + t0) = pl.u;
    red[threadIdx.x] = e[0] + e[1] + e[2] + e[3];
    __syncthreads();
    #pragma unroll
    for (int o = 128; o > 0; o >>= 1) {
        if (threadIdx.x < o) red[threadIdx.x] += red[threadIdx.x + o];
        __syncthreads();
    }
    if (threadIdx.x == 0) invr[b * NN + s] = 1.0f / red[0];
}

// ---------------- host ----------------
extern "C" void kernel_launch(void* const* d_in, const int* in_sizes, int n_in,
                              void* d_out, int out_size)
{
    const float* f1 = (const float*)d_in[0];
    const float* f2 = (const float*)d_in[1];
    const float* W  = (const float*)d_in[2];
    float* out1 = (float*)d_out;
    float* out2 = out1 + ((size_t)NB << 20);

    __nv_bfloat16 *f1h, *f1l, *f2h, *f2l, *wth, *wtl, *a1h, *a1l, *eth, *etl, *erh, *erl;
    float *cc, *part, *mc, *invc, *invr;
    cudaGetSymbolAddress((void**)&f1h, g_f1h); cudaGetSymbolAddress((void**)&f1l, g_f1l);
    cudaGetSymbolAddress((void**)&f2h, g_f2h); cudaGetSymbolAddress((void**)&f2l, g_f2l);
    cudaGetSymbolAddress((void**)&wth, g_wth); cudaGetSymbolAddress((void**)&wtl, g_wtl);
    cudaGetSymbolAddress((void**)&a1h, g_a1h); cudaGetSymbolAddress((void**)&a1l, g_a1l);
    cudaGetSymbolAddress((void**)&eth, g_eth); cudaGetSymbolAddress((void**)&etl, g_etl);
    cudaGetSymbolAddress((void**)&erh, g_erh); cudaGetSymbolAddress((void**)&erl, g_erl);
    cudaGetSymbolAddress((void**)&cc, g_cc);   cudaGetSymbolAddress((void**)&part, g_part);
    cudaGetSymbolAddress((void**)&mc, g_mc);   cudaGetSymbolAddress((void**)&invc, g_invc);
    cudaGetSymbolAddress((void**)&invr, g_invr);

    cudaFuncSetAttribute(gemm_kernel<true,  false>, cudaFuncAttributeMaxDynamicSharedMemorySize, SMEM_DYN);
    cudaFuncSetAttribute(gemm_kernel<false, false>, cudaFuncAttributeMaxDynamicSharedMemorySize, SMEM_DYN);
    cudaFuncSetAttribute(gemm_kernel<false, true>,  cudaFuncAttributeMaxDynamicSharedMemorySize, SMEM_DYN);

    const size_t MBe = (size_t)1 << 20;
    dim3 gg(8, 8, NB);   // 128x128 tiles

    // splits
    split_kernel<<<16384, 256>>>(f1, f1h, f1l);
    split_kernel<<<16384, 256>>>(f2, f2h, f2l);
    wtrans_kernel<<<dim3(32, 32), dim3(32, 8)>>>(W, wth, wtl);

    // 1. a1 = f1 @ W  (B operand = W^T rows, shared across batch) -> split bf16
    gemm_kernel<true,  false><<<gg, 256, SMEM_DYN>>>(f1h, f1l, wth, wtl,
                                                     nullptr, a1h, a1l, nullptr, MBe, 0, MBe);
    // 2. cc = a1 @ f2^T -> fp32
    gemm_kernel<false, false><<<gg, 256, SMEM_DYN>>>(a1h, a1l, f2h, f2l,
                                                     cc, nullptr, nullptr, nullptr, MBe, MBe, MBe);
    // 3-4. column softmax stats (two-stage parallel reductions)
    pmax_kernel<<<dim3(4, 8, NB), 256>>>(cc, part);
    maxred_kernel<<<dim3(4, NB), 256>>>(part, mc);
    psum_kernel<<<dim3(4, 8, NB), 256>>>(cc, mc, part);
    sumred_kernel<<<dim3(4, NB), 256>>>(part, invc);
    // 5. E_T split (transposed)
    expT_kernel<<<dim3(32, 32, NB), dim3(32, 8)>>>(cc, mc, eth, etl);
    // 6. out1[t,s] = invc[t] * sum_d E_T[t,d] * f1[s,d]
    gemm_kernel<false, true><<<gg, 256, SMEM_DYN>>>(eth, etl, f1h, f1l,
                                                    out1, nullptr, nullptr, invc, MBe, MBe, MBe);
    // 7. row softmax split
    exprow_kernel<<<dim3(NN, NB), 256>>>(cc, erh, erl, invr);
    // 8. out2[s,t] = invr[s] * sum_d E_r[s,d] * f2[t,d]
    gemm_kernel<false, true><<<gg, 256, SMEM_DYN>>>(erh, erl, f2h, f2l,
                                                    out2, nullptr, nullptr, invr, MBe, MBe, MBe);
}

// round 4
// speedup vs baseline: 2.6479x; 1.1714x over previous
#include <cuda_runtime.h>
#include <cuda_bf16.h>
#include <math.h>
#include <stdint.h>

#define NB 16
#define NN 1024

// ---------------- helpers ----------------
__device__ __forceinline__ uint32_t smem_to_u32(const void* p) {
    uint32_t a;
    asm("{ .reg .u64 t; cvta.to.shared.u64 t, %1; cvt.u32.u64 %0, t; }" : "=r"(a) : "l"(p));
    return a;
}
__device__ __forceinline__ void cp16(uint32_t dst, const void* src) {
    asm volatile("cp.async.cg.shared.global [%0], [%1], 16;" :: "r"(dst), "l"(src));
}
__device__ __forceinline__ void cp_commit() { asm volatile("cp.async.commit_group;" ::: "memory"); }
__device__ __forceinline__ void cp_wait1()  { asm volatile("cp.async.wait_group 1;" ::: "memory"); }
__device__ __forceinline__ void cp_wait0()  { asm volatile("cp.async.wait_group 0;" ::: "memory"); }

__device__ __forceinline__ void ldsm4(uint32_t* r, uint32_t addr) {
    asm volatile("ldmatrix.sync.aligned.m8n8.x4.shared.b16 {%0,%1,%2,%3}, [%4];"
                 : "=r"(r[0]), "=r"(r[1]), "=r"(r[2]), "=r"(r[3]) : "r"(addr));
}
__device__ __forceinline__ void mma_bf16(float* c, const uint32_t* a, const uint32_t* b) {
    asm volatile(
        "mma.sync.aligned.m16n8k16.row.col.f32.bf16.bf16.f32 "
        "{%0,%1,%2,%3}, {%4,%5,%6,%7}, {%8,%9}, {%0,%1,%2,%3};"
        : "+f"(c[0]), "+f"(c[1]), "+f"(c[2]), "+f"(c[3])
        : "r"(a[0]), "r"(a[1]), "r"(a[2]), "r"(a[3]), "r"(b[0]), "r"(b[1]));
}

// ---------------- scratch (device globals) ----------------
#define TOT ((size_t)NB * NN * NN)
__device__ __nv_bfloat16 g_f1h[TOT], g_f1l[TOT];
__device__ __nv_bfloat16 g_f2h[TOT], g_f2l[TOT];
__device__ __nv_bfloat16 g_wth[NN * NN], g_wtl[NN * NN];
__device__ __nv_bfloat16 g_a1h[TOT], g_a1l[TOT];
__device__ __nv_bfloat16 g_eth[TOT], g_etl[TOT];
__device__ __nv_bfloat16 g_erh[TOT], g_erl[TOT];
__device__ float g_cc[TOT];
__device__ float g_part[NB * 8 * NN];
__device__ float g_mc[NB * NN], g_invc[NB * NN], g_invr[NB * NN];

// ---------------- split-2 bf16 GEMM via mma.sync ----------------
// C[M,N] = A[M,K] · B[N,K]^T, hi/lo split operands (3 products).
// Tile 128x128, BK=32, 8 warps (2m x 4n), warp tile 64x32, 2-stage cp.async,
// 2 CTAs/SM. Product-major mma ordering (16 independent accs between reuse).
#define BK 32
#define LDSROW 40                       // bf16 per smem row (32 + 8 pad)
#define ARRB (128 * LDSROW * 2)         // 10240 B per operand array
#define SLOTB (4 * ARRB)                // 40960 B per stage
#define NSTAGE 2
#define SMEM_DYN (NSTAGE * SLOTB)       // 81920 B -> 2 CTAs/SM
#define KT 32                           // k tiles

template<bool SPLIT_OUT, bool SCALE>
__global__ __launch_bounds__(256, 2)
void gemm_kernel(const __nv_bfloat16* __restrict__ Ah, const __nv_bfloat16* __restrict__ Al,
                 const __nv_bfloat16* __restrict__ Bh, const __nv_bfloat16* __restrict__ Bl,
                 float* __restrict__ C, __nv_bfloat16* __restrict__ Ch, __nv_bfloat16* __restrict__ Cl,
                 const float* __restrict__ scaleg, size_t sA, size_t sB, size_t sC)
{
    extern __shared__ char dsm[];
    const uint32_t sb = smem_to_u32(dsm);

    const int tid = threadIdx.x;
    const int lane = tid & 31;
    const int w = tid >> 5;
    const int wm = w & 1;        // 0..1 -> 64 rows each
    const int wn = w >> 1;       // 0..3 -> 32 cols each
    const int b = blockIdx.z;
    const int m0 = blockIdx.y * 128;
    const int n0 = blockIdx.x * 128;

    Ah += (size_t)b * sA; Al += (size_t)b * sA;
    Bh += (size_t)b * sB; Bl += (size_t)b * sB;

    float acc[4][4][4];
    #pragma unroll
    for (int i = 0; i < 4; i++)
        #pragma unroll
        for (int j = 0; j < 4; j++)
            #pragma unroll
            for (int q = 0; q < 4; q++) acc[i][j][q] = 0.0f;

    auto load_stage = [&](int slot, int kt) {
        uint32_t base = sb + slot * SLOTB;
        int k0 = kt * BK;
        #pragma unroll
        for (int i = 0; i < 2; i++) {
            int f = tid + i * 256;
            int row = f >> 2, ch = f & 3;
            uint32_t so = row * (LDSROW * 2) + ch * 16;
            size_t gA = ((size_t)(m0 + row) << 10) + k0 + ch * 8;
            size_t gB = ((size_t)(n0 + row) << 10) + k0 + ch * 8;
            cp16(base + 0 * ARRB + so, Ah + gA);
            cp16(base + 1 * ARRB + so, Al + gA);
            cp16(base + 2 * ARRB + so, Bh + gB);
            cp16(base + 3 * ARRB + so, Bl + gB);
        }
        cp_commit();
    };

    load_stage(0, 0);

    const int arow = wm * 64 + (lane & 15);                      // + mt*16
    const int achk_l = lane >> 4;                                // + 2*ks
    const int brow = wn * 32 + ((lane & 16) >> 1) + (lane & 7);  // + p*16
    const int bchk_l = (lane >> 3) & 1;                          // + 2*ks

    for (int kt = 0; kt < KT; kt++) {
        if (kt + 1 < KT) {
            load_stage((kt + 1) & 1, kt + 1);
            cp_wait1();
        } else {
            cp_wait0();
        }
        __syncthreads();

        uint32_t sa = sb + (kt & 1) * SLOTB;
        #pragma unroll
        for (int ks = 0; ks < 2; ks++) {
            uint32_t a_h[4][4], a_l[4][4], b_h[2][4], b_l[2][4];
            #pragma unroll
            for (int mt = 0; mt < 4; mt++) {
                uint32_t ad = sa + (arow + mt * 16) * (LDSROW * 2) + (ks * 2 + achk_l) * 16;
                ldsm4(a_h[mt], ad);
                ldsm4(a_l[mt], ad + ARRB);
            }
            #pragma unroll
            for (int p = 0; p < 2; p++) {
                uint32_t bd = sa + 2 * ARRB + (brow + p * 16) * (LDSROW * 2) + (ks * 2 + bchk_l) * 16;
                ldsm4(b_h[p], bd);
                ldsm4(b_l[p], bd + ARRB);
            }
            // product-major: all accumulators visited once per pass
            #pragma unroll
            for (int mt = 0; mt < 4; mt++)
                #pragma unroll
                for (int nt = 0; nt < 4; nt++)
                    mma_bf16(acc[mt][nt], a_h[mt], &b_h[nt >> 1][(nt & 1) * 2]);
            #pragma unroll
            for (int mt = 0; mt < 4; mt++)
                #pragma unroll
                for (int nt = 0; nt < 4; nt++)
                    mma_bf16(acc[mt][nt], a_h[mt], &b_l[nt >> 1][(nt & 1) * 2]);
            #pragma unroll
            for (int mt = 0; mt < 4; mt++)
                #pragma unroll
                for (int nt = 0; nt < 4; nt++)
                    mma_bf16(acc[mt][nt], a_l[mt], &b_h[nt >> 1][(nt & 1) * 2]);
        }
        __syncthreads();
    }

    // ---- epilogue: direct global stores ----
    #pragma unroll
    for (int mt = 0; mt < 4; mt++) {
        int mr = m0 + wm * 64 + mt * 16 + (lane >> 2);
        float s0 = 1.0f, s1 = 1.0f;
        if (SCALE) {
            s0 = scaleg[b * NN + mr];
            s1 = scaleg[b * NN + mr + 8];
        }
        #pragma unroll
        for (int nt = 0; nt < 4; nt++) {
            int nc = n0 + wn * 32 + nt * 8 + (lane & 3) * 2;
            size_t i0 = (size_t)b * sC + ((size_t)mr << 10) + nc;
            size_t i1 = i0 + (8 << 10);
            float v00 = acc[mt][nt][0] * s0, v01 = acc[mt][nt][1] * s0;
            float v10 = acc[mt][nt][2] * s1, v11 = acc[mt][nt][3] * s1;
            if (SPLIT_OUT) {
                __nv_bfloat16 h00 = __float2bfloat16(v00), h01 = __float2bfloat16(v01);
                __nv_bfloat16 h10 = __float2bfloat16(v10), h11 = __float2bfloat16(v11);
                *(__nv_bfloat162*)(Ch + i0) = __nv_bfloat162(h00, h01);
                *(__nv_bfloat162*)(Ch + i1) = __nv_bfloat162(h10, h11);
                *(__nv_bfloat162*)(Cl + i0) = __nv_bfloat162(
                    __float2bfloat16(v00 - __bfloat162float(h00)),
                    __float2bfloat16(v01 - __bfloat162float(h01)));
                *(__nv_bfloat162*)(Cl + i1) = __nv_bfloat162(
                    __float2bfloat16(v10 - __bfloat162float(h10)),
                    __float2bfloat16(v11 - __bfloat162float(h11)));
            } else {
                *(float2*)(C + i0) = make_float2(v00, v01);
                *(float2*)(C + i1) = make_float2(v10, v11);
            }
        }
    }
}

// ---------------- elementwise / reduction kernels ----------------
__global__ void split_kernel(const float* __restrict__ x, __nv_bfloat16* __restrict__ h,
                             __nv_bfloat16* __restrict__ l)
{
    size_t i = ((size_t)blockIdx.x * 256 + threadIdx.x) * 4;
    float4 v = *(const float4*)(x + i);
    union { __nv_bfloat16 hh[4]; uint2 u; } ph, pl;
    float f[4] = {v.x, v.y, v.z, v.w};
    #pragma unroll
    for (int j = 0; j < 4; j++) {
        __nv_bfloat16 bb = __float2bfloat16(f[j]);
        ph.hh[j] = bb;
        pl.hh[j] = __float2bfloat16(f[j] - __bfloat162float(bb));
    }
    *(uint2*)(h + i) = ph.u;
    *(uint2*)(l + i) = pl.u;
}

__global__ void wtrans_kernel(const float* __restrict__ W, __nv_bfloat16* __restrict__ h,
                              __nv_bfloat16* __restrict__ l)
{
    __shared__ float tile[32][33];
    int e0 = blockIdx.x << 5, d0 = blockIdx.y << 5;
    int tx = threadIdx.x, ty = threadIdx.y;
    #pragma unroll
    for (int j = 0; j < 4; j++) {
        int r = ty + (j << 3);
        tile[r][tx] = W[(size_t)(d0 + r) * NN + e0 + tx];
    }
    __syncthreads();
    #pragma unroll
    for (int j = 0; j < 4; j++) {
        int r = ty + (j << 3);
        float v = tile[tx][r];                      // W[d0+tx][e0+r]
        __nv_bfloat16 hh = __float2bfloat16(v);
        size_t o = (size_t)(e0 + r) * NN + d0 + tx; // WT[e][d]
        h[o] = hh;
        l[o] = __float2bfloat16(v - __bfloat162float(hh));
    }
}

__global__ void pmax_kernel(const float* __restrict__ cc, float* __restrict__ part)
{
    int b = blockIdx.z, sc = blockIdx.y;
    int t = blockIdx.x * 256 + threadIdx.x;
    const float* p = cc + ((size_t)b << 20) + ((size_t)sc << 17) + t;
    float m = -INFINITY;
    #pragma unroll 8
    for (int s = 0; s < 128; s++) m = fmaxf(m, p[(size_t)s << 10]);
    part[((b << 3) + sc) * NN + t] = m;
}
__global__ void maxred_kernel(const float* __restrict__ part, float* __restrict__ mc)
{
    int b = blockIdx.y;
    int t = blockIdx.x * 256 + threadIdx.x;
    float m = -INFINITY;
    #pragma unroll
    for (int c = 0; c < 8; c++) m = fmaxf(m, part[((b << 3) + c) * NN + t]);
    mc[b * NN + t] = m;
}
__global__ void psum_kernel(const float* __restrict__ cc, const float* __restrict__ mc,
                            float* __restrict__ part)
{
    int b = blockIdx.z, sc = blockIdx.y;
    int t = blockIdx.x * 256 + threadIdx.x;
    const float* p = cc + ((size_t)b << 20) + ((size_t)sc << 17) + t;
    float mm = mc[b * NN + t];
    float sum = 0.0f;
    #pragma unroll 4
    for (int s = 0; s < 128; s++) sum += expf(p[(size_t)s << 10] - mm);
    part[((b << 3) + sc) * NN + t] = sum;
}
__global__ void sumred_kernel(const float* __restrict__ part, float* __restrict__ invc)
{
    int b = blockIdx.y;
    int t = blockIdx.x * 256 + threadIdx.x;
    float s = 0.0f;
    #pragma unroll
    for (int c = 0; c < 8; c++) s += part[((b << 3) + c) * NN + t];
    invc[b * NN + t] = 1.0f / s;
}

// E_T[t][s] = exp(cc[s][t] - mc[t]) split into bf16 hi/lo (transposed write)
__global__ void expT_kernel(const float* __restrict__ cc, const float* __restrict__ mc,
                            __nv_bfloat16* __restrict__ Eh, __nv_bfloat16* __restrict__ El)
{
    __shared__ float tile[32][33];
    int b = blockIdx.z;
    int s0 = blockIdx.x << 5, t0 = blockIdx.y << 5;
    int tx = threadIdx.x, ty = threadIdx.y;
    size_t cb = (size_t)b << 20;
    #pragma unroll
    for (int j = 0; j < 4; j++) {
        int r = ty + (j << 3);
        tile[r][tx] = cc[cb + ((size_t)(s0 + r) << 10) + t0 + tx];
    }
    __syncthreads();
    #pragma unroll
    for (int j = 0; j < 4; j++) {
        int r = ty + (j << 3);
        float m = mc[b * NN + t0 + r];
        float e = expf(tile[tx][r] - m);            // cc[s0+tx][t0+r]
        __nv_bfloat16 hh = __float2bfloat16(e);
        size_t o = cb + ((size_t)(t0 + r) << 10) + s0 + tx;
        Eh[o] = hh;
        El[o] = __float2bfloat16(e - __bfloat162float(hh));
    }
}

// row softmax: E_r split + invr
__global__ void exprow_kernel(const float* __restrict__ cc, __nv_bfloat16* __restrict__ Eh,
                              __nv_bfloat16* __restrict__ El, float* __restrict__ invr)
{
    __shared__ float red[256];
    int b = blockIdx.y, s = blockIdx.x;
    size_t base = ((size_t)b << 20) + ((size_t)s << 10);
    int t0 = threadIdx.x * 4;
    float4 q = *(const float4*)(cc + base + t0);
    float m = fmaxf(fmaxf(q.x, q.y), fmaxf(q.z, q.w));
    red[threadIdx.x] = m;
    __syncthreads();
    #pragma unroll
    for (int o = 128; o > 0; o >>= 1) {
        if (threadIdx.x < o) red[threadIdx.x] = fmaxf(red[threadIdx.x], red[threadIdx.x + o]);
        __syncthreads();
    }
    m = red[0];
    __syncthreads();
    float e[4] = {expf(q.x - m), expf(q.y - m), expf(q.z - m), expf(q.w - m)};
    union { __nv_bfloat16 h[4]; uint2 u; } ph, pl;
    #pragma unroll
    for (int j = 0; j < 4; j++) {
        __nv_bfloat16 hh = __float2bfloat16(e[j]);
        ph.h[j] = hh;
        pl.h[j] = __float2bfloat16(e[j] - __bfloat162float(hh));
    }
    *(uint2*)(Eh + base + t0) = ph.u;
    *(uint2*)(El + base + t0) = pl.u;
    red[threadIdx.x] = e[0] + e[1] + e[2] + e[3];
    __syncthreads();
    #pragma unroll
    for (int o = 128; o > 0; o >>= 1) {
        if (threadIdx.x < o) red[threadIdx.x] += red[threadIdx.x + o];
        __syncthreads();
    }
    if (threadIdx.x == 0) invr[b * NN + s] = 1.0f / red[0];
}

// ---------------- host ----------------
extern "C" void kernel_launch(void* const* d_in, const int* in_sizes, int n_in,
                              void* d_out, int out_size)
{
    const float* f1 = (const float*)d_in[0];
    const float* f2 = (const float*)d_in[1];
    const float* W  = (const float*)d_in[2];
    float* out1 = (float*)d_out;
    float* out2 = out1 + ((size_t)NB << 20);

    __nv_bfloat16 *f1h, *f1l, *f2h, *f2l, *wth, *wtl, *a1h, *a1l, *eth, *etl, *erh, *erl;
    float *cc, *part, *mc, *invc, *invr;
    cudaGetSymbolAddress((void**)&f1h, g_f1h); cudaGetSymbolAddress((void**)&f1l, g_f1l);
    cudaGetSymbolAddress((void**)&f2h, g_f2h); cudaGetSymbolAddress((void**)&f2l, g_f2l);
    cudaGetSymbolAddress((void**)&wth, g_wth); cudaGetSymbolAddress((void**)&wtl, g_wtl);
    cudaGetSymbolAddress((void**)&a1h, g_a1h); cudaGetSymbolAddress((void**)&a1l, g_a1l);
    cudaGetSymbolAddress((void**)&eth, g_eth); cudaGetSymbolAddress((void**)&etl, g_etl);
    cudaGetSymbolAddress((void**)&erh, g_erh); cudaGetSymbolAddress((void**)&erl, g_erl);
    cudaGetSymbolAddress((void**)&cc, g_cc);   cudaGetSymbolAddress((void**)&part, g_part);
    cudaGetSymbolAddress((void**)&mc, g_mc);   cudaGetSymbolAddress((void**)&invc, g_invc);
    cudaGetSymbolAddress((void**)&invr, g_invr);

    cudaFuncSetAttribute(gemm_kernel<true,  false>, cudaFuncAttributeMaxDynamicSharedMemorySize, SMEM_DYN);
    cudaFuncSetAttribute(gemm_kernel<false, false>, cudaFuncAttributeMaxDynamicSharedMemorySize, SMEM_DYN);
    cudaFuncSetAttribute(gemm_kernel<false, true>,  cudaFuncAttributeMaxDynamicSharedMemorySize, SMEM_DYN);

    const size_t MBe = (size_t)1 << 20;
    dim3 gg(8, 8, NB);   // 128x128 tiles

    // splits
    split_kernel<<<16384, 256>>>(f1, f1h, f1l);
    split_kernel<<<16384, 256>>>(f2, f2h, f2l);
    wtrans_kernel<<<dim3(32, 32), dim3(32, 8)>>>(W, wth, wtl);

    // 1. a1 = f1 @ W  -> split bf16
    gemm_kernel<true,  false><<<gg, 256, SMEM_DYN>>>(f1h, f1l, wth, wtl,
                                                     nullptr, a1h, a1l, nullptr, MBe, 0, MBe);
    // 2. cc = a1 @ f2^T -> fp32
    gemm_kernel<false, false><<<gg, 256, SMEM_DYN>>>(a1h, a1l, f2h, f2l,
                                                     cc, nullptr, nullptr, nullptr, MBe, MBe, MBe);
    // 3-4. column softmax stats
    pmax_kernel<<<dim3(4, 8, NB), 256>>>(cc, part);
    maxred_kernel<<<dim3(4, NB), 256>>>(part, mc);
    psum_kernel<<<dim3(4, 8, NB), 256>>>(cc, mc, part);
    sumred_kernel<<<dim3(4, NB), 256>>>(part, invc);
    // 5. E_T split (transposed)
    expT_kernel<<<dim3(32, 32, NB), dim3(32, 8)>>>(cc, mc, eth, etl);
    // 6. out1[t,s] = invc[t] * sum_d E_T[t,d] * f1[s,d]
    gemm_kernel<false, true><<<gg, 256, SMEM_DYN>>>(eth, etl, f1h, f1l,
                                                    out1, nullptr, nullptr, invc, MBe, MBe, MBe);
    // 7. row softmax split
    exprow_kernel<<<dim3(NN, NB), 256>>>(cc, erh, erl, invr);
    // 8. out2[s,t] = invr[s] * sum_d E_r[s,d] * f2[t,d]
    gemm_kernel<false, true><<<gg, 256, SMEM_DYN>>>(erh, erl, f2h, f2l,
                                                    out2, nullptr, nullptr, invr, MBe, MBe, MBe);
}